// round 13
// baseline (speedup 1.0000x reference)
#include <cuda_runtime.h>
#include <math.h>

#define BB   32      // batch
#define LL   1024    // seq len
#define CC   34      // channels in x
#define DD   256     // model dim
#define EE   8       // experts
#define NQ   4       // patches that survive truncation (1024/256)
#define TT   (BB*NQ) // 128 token-patches
#define PRED 96

// ---------------- scratch (no allocations allowed) ----------------
__device__ float g_mean[BB];
__device__ float g_std[BB];
__device__ float g_xp[TT][DD];        // projected patches
__device__ float g_gates[TT][EE];     // router gates
__device__ float g_comb[TT][DD];      // gate-combined expert output
__device__ float g_Wt[EE][DD][DD];    // W_experts transposed: [e][d][h]

// packed fp32x2 helpers
__device__ __forceinline__ unsigned long long pack2(float lo, float hi) {
    unsigned long long r;
    asm("mov.b64 %0, {%1, %2};" : "=l"(r) : "f"(lo), "f"(hi));
    return r;
}
__device__ __forceinline__ void unpack2(unsigned long long v, float& lo, float& hi) {
    asm("mov.b64 {%0, %1}, %2;" : "=f"(lo), "=f"(hi) : "l"(v));
}
__device__ __forceinline__ unsigned long long fma2(unsigned long long a,
                                                   unsigned long long b,
                                                   unsigned long long c) {
    unsigned long long r;
    asm("fma.rn.f32x2 %0, %1, %2, %3;" : "=l"(r) : "l"(a), "l"(b), "l"(c));
    return r;
}

// ---------------- K1: fused (stats+proj+router) || float4 transpose ----------------
// blocks [0,32): per-b stats + patch proj + router softmax.
// blocks [32,160): one 64x64 transpose tile each (8 e x 16 tiles).
union SmemU {
    struct { float tile[64][65]; } tr;                         // 16.6 KB
    struct {
        float Wp_t[16][DD + 1];
        float Wr[EE][DD];
        float xc[64];
        float xp[NQ][DD];
        float red[2][8];
        float logit[32];
        float mean, std;
    } st;                                                       // ~28.8 KB
};

__global__ __launch_bounds__(256) void k_prep(const float* __restrict__ W,
                                              const float* __restrict__ x,
                                              const float* __restrict__ W_proj,
                                              const float* __restrict__ b_proj,
                                              const float* __restrict__ W_router,
                                              const float* __restrict__ b_router)
{
    __shared__ SmemU sm;
    int bid = blockIdx.x, tid = threadIdx.x;

    if (bid >= 32) {
        // ---- float4 transpose of one 64x64 tile ----
        int tl  = bid - 32;              // 0..127
        int e   = tl >> 4;
        int rem = tl & 15;
        int h0  = (rem >> 2) * 64;
        int d0  = (rem & 3) * 64;
        const float* We = W + e * DD * DD;

        int c4 = tid & 15, r = tid >> 4;      // 16 float4-cols x 16 rows
        float4 v[4];
        #pragma unroll
        for (int i = 0; i < 4; i++)
            v[i] = *(const float4*)&We[(h0 + r + 16 * i) * DD + d0 + c4 * 4];
        #pragma unroll
        for (int i = 0; i < 4; i++) {
            int row = r + 16 * i;
            sm.tr.tile[row][c4 * 4 + 0] = v[i].x;
            sm.tr.tile[row][c4 * 4 + 1] = v[i].y;
            sm.tr.tile[row][c4 * 4 + 2] = v[i].z;
            sm.tr.tile[row][c4 * 4 + 3] = v[i].w;
        }
        __syncthreads();
        int hc4 = tid & 15, dr = tid >> 4;
        #pragma unroll
        for (int i = 0; i < 4; i++) {
            int dl = dr + 16 * i;
            float4 o;
            o.x = sm.tr.tile[hc4 * 4 + 0][dl];
            o.y = sm.tr.tile[hc4 * 4 + 1][dl];
            o.z = sm.tr.tile[hc4 * 4 + 2][dl];
            o.w = sm.tr.tile[hc4 * 4 + 3][dl];
            *(float4*)&g_Wt[e][d0 + dl][h0 + hc4 * 4] = o;
        }
        return;
    }

    // ---- stats + proj + router path ----
    int b = bid;
    #pragma unroll
    for (int i = 0; i < 16; i++) {
        int idx = tid + i * 256;            // idx = d*16 + j
        sm.st.Wp_t[idx & 15][idx >> 4] = W_proj[idx];
    }
    #pragma unroll
    for (int i = 0; i < 8; i++) {
        int idx = tid + i * 256;
        sm.st.Wr[idx >> 8][idx & 255] = W_router[idx];
    }

    const float* xb = x + (long)b * LL * CC + 2;
    float v0 = xb[(tid      ) * CC];
    float v1 = xb[(tid + 256) * CC];
    float v2 = xb[(tid + 512) * CC];
    float v3 = xb[(tid + 768) * CC];
    float s1 = v0 + v1 + v2 + v3;
    float s2 = v0*v0 + v1*v1 + v2*v2 + v3*v3;
    #pragma unroll
    for (int o = 16; o; o >>= 1) {
        s1 += __shfl_down_sync(0xffffffffu, s1, o);
        s2 += __shfl_down_sync(0xffffffffu, s2, o);
    }
    if ((tid & 31) == 0) { sm.st.red[0][tid >> 5] = s1; sm.st.red[1][tid >> 5] = s2; }
    __syncthreads();
    if (tid == 0) {
        float a = 0.f, c = 0.f;
        #pragma unroll
        for (int i = 0; i < 8; i++) { a += sm.st.red[0][i]; c += sm.st.red[1][i]; }
        float m   = a / (float)LL;
        float var = c / (float)LL - m * m;
        float sd  = sqrtf(var + 1e-5f);
        sm.st.mean = m; sm.st.std = sd;
        g_mean[b] = m; g_std[b] = sd;
    }
    __syncthreads();
    float m = sm.st.mean, sd = sm.st.std;
    if (tid < 64) sm.st.xc[tid] = (v0 - m) / sd;   // v0 holds l = tid
    __syncthreads();

    // xp[q][d], thread owns d = tid
    float bp = b_proj[tid];
    #pragma unroll
    for (int q = 0; q < NQ; q++) {
        float acc = bp;
        #pragma unroll
        for (int j = 0; j < 16; j++)
            acc += sm.st.Wp_t[j][tid] * sm.st.xc[q * 16 + j];
        sm.st.xp[q][tid] = acc;
        g_xp[b * NQ + q][tid] = acc;
    }
    __syncthreads();

    // router logits: thread = (pair = tid>>3, k = tid&7)
    {
        int pair = tid >> 3, k = tid & 7;
        int q = pair >> 3, e = pair & 7;
        float acc = 0.f;
        #pragma unroll
        for (int i = 0; i < 32; i++) {
            int ii = (i + tid) & 31;
            int d = k * 32 + ii;
            acc += sm.st.Wr[e][d] * sm.st.xp[q][d];
        }
        acc += __shfl_down_sync(0xffffffffu, acc, 4, 8);
        acc += __shfl_down_sync(0xffffffffu, acc, 2, 8);
        acc += __shfl_down_sync(0xffffffffu, acc, 1, 8);
        if (k == 0) sm.st.logit[pair] = acc + b_router[e];
    }
    __syncthreads();
    if (tid < NQ) {
        int q = tid;
        float mx = -1e30f;
        #pragma unroll
        for (int e = 0; e < 8; e++) mx = fmaxf(mx, sm.st.logit[q * 8 + e]);
        float s = 0.f, ex[8];
        #pragma unroll
        for (int e = 0; e < 8; e++) { ex[e] = __expf(sm.st.logit[q * 8 + e] - mx); s += ex[e]; }
        float inv = 1.f / s;
        #pragma unroll
        for (int e = 0; e < 8; e++) g_gates[b * NQ + q][e] = ex[e] * inv;
    }
}

// ---------------- K2: expert GEMM + gate-combine ----------------
// CTA = (tt = bid>>4: 16 tokens, ht = bid&15: 16 h). 256 thr.
// thread = (e = tid>>5, hg: h-quad, tg: token pair) -> 8 outputs.
// Per d: 1 broadcast LDG.128 (h-quad) + 1 LDS.64 (token pair) + 4 FFMA2.
__global__ __launch_bounds__(256) void k_expert(const float* __restrict__ b_experts)
{
    __shared__ float xps[DD][18];      // [d][t], 8B-aligned token pairs
    __shared__ float g_sh[16][EE];     // [t][e]
    __shared__ float sred[EE][16][17]; // [e][h][t]

    int bid = blockIdx.x, tid = threadIdx.x;
    int tt = bid >> 4, ht = bid & 15;
    int t0 = tt * 16, h0 = ht * 16;

    // stage xp transposed: 16 tokens x 256 d
    #pragma unroll
    for (int k = 0; k < 16; k++) {
        int idx = tid + k * 256;         // 4096
        int t = idx >> 8, d = idx & 255;
        xps[d][t] = g_xp[t0 + t][d];
    }
    if (tid < 128) g_sh[tid >> 3][tid & 7] = g_gates[t0 + (tid >> 3)][tid & 7];
    __syncthreads();

    int e  = tid >> 5;
    int sub = tid & 31;
    int hg = sub & 3;         // h-quad: h0 + hg*4 .. +3
    int tg = sub >> 2;        // token pair: 2tg, 2tg+1
    const float4* wp = (const float4*)&g_Wt[e][0][h0 + hg * 4];

    unsigned long long acc00 = 0ull, acc01 = 0ull, acc10 = 0ull, acc11 = 0ull;
    #pragma unroll 8
    for (int d = 0; d < DD; d++) {
        float4 w4 = wp[(long)d * (DD / 4)];
        unsigned long long wp01 = pack2(w4.x, w4.y);
        unsigned long long wp23 = pack2(w4.z, w4.w);
        float xa, xb2;
        unpack2(*(const unsigned long long*)&xps[d][2 * tg], xa, xb2);
        unsigned long long xd0 = pack2(xa, xa);
        unsigned long long xd1 = pack2(xb2, xb2);
        acc00 = fma2(wp01, xd0, acc00);   // h(+0,+1), token 0
        acc01 = fma2(wp01, xd1, acc01);   // h(+0,+1), token 1
        acc10 = fma2(wp23, xd0, acc10);   // h(+2,+3), token 0
        acc11 = fma2(wp23, xd1, acc11);   // h(+2,+3), token 1
    }
    float4 be4 = *(const float4*)&b_experts[e * DD + h0 + hg * 4];
    float gate0 = g_sh[2 * tg + 0][e];
    float gate1 = g_sh[2 * tg + 1][e];
    float lo, hi;
    unpack2(acc00, lo, hi);
    sred[e][hg * 4 + 0][2 * tg + 0] = gate0 * (lo + be4.x);
    sred[e][hg * 4 + 1][2 * tg + 0] = gate0 * (hi + be4.y);
    unpack2(acc01, lo, hi);
    sred[e][hg * 4 + 0][2 * tg + 1] = gate1 * (lo + be4.x);
    sred[e][hg * 4 + 1][2 * tg + 1] = gate1 * (hi + be4.y);
    unpack2(acc10, lo, hi);
    sred[e][hg * 4 + 2][2 * tg + 0] = gate0 * (lo + be4.z);
    sred[e][hg * 4 + 3][2 * tg + 0] = gate0 * (hi + be4.w);
    unpack2(acc11, lo, hi);
    sred[e][hg * 4 + 2][2 * tg + 1] = gate1 * (lo + be4.z);
    sred[e][hg * 4 + 3][2 * tg + 1] = gate1 * (hi + be4.w);
    __syncthreads();

    // combine over e: thread = (t = tid>>4, h = tid&15)
    int t = tid >> 4, h = tid & 15;
    float s = 0.f;
    #pragma unroll
    for (int e2 = 0; e2 < EE; e2++) s += sred[e2][h][t];
    g_comb[t0 + t][h0 + h] = s;
}

// ---------------- K3: head GEMV, grid = 12 p-tiles x 8 b-quads ----------------
__global__ __launch_bounds__(256) void k_head(
    const float* __restrict__ W_head, const float* __restrict__ b_head,
    float* __restrict__ out)
{
    __shared__ float fl[4][LL];
    int pt = blockIdx.x;          // 0..11
    int bq = blockIdx.y;          // 0..7
    int b0 = bq * 4;
    int tid = threadIdx.x;

    #pragma unroll
    for (int i = 0; i < 16; i++) {
        int idx = tid + i * 256;               // 4096 = 4 b * 1024
        int bb = idx >> 10, l = idx & 1023;
        fl[bb][l] = g_comb[(b0 + bb) * NQ + (l >> 8)][l & 255];
    }
    __syncthreads();

    int warp = tid >> 5, lane = tid & 31;
    int p = pt * 8 + warp;
    const float4* W4 = (const float4*)(W_head + p * LL);
    const float4* f0 = (const float4*)fl[0];
    const float4* f1 = (const float4*)fl[1];
    const float4* f2 = (const float4*)fl[2];
    const float4* f3 = (const float4*)fl[3];

    float a0 = 0.f, a1 = 0.f, a2 = 0.f, a3 = 0.f, s = 0.f;
    #pragma unroll
    for (int i = 0; i < 8; i++) {
        int off = i * 32 + lane;
        float4 w = W4[off];                    // coalesced 512B
        float4 x0 = f0[off], x1 = f1[off], x2 = f2[off], x3 = f3[off];
        a0 += w.x * x0.x + w.y * x0.y + w.z * x0.z + w.w * x0.w;
        a1 += w.x * x1.x + w.y * x1.y + w.z * x1.z + w.w * x1.w;
        a2 += w.x * x2.x + w.y * x2.y + w.z * x2.z + w.w * x2.w;
        a3 += w.x * x3.x + w.y * x3.y + w.z * x3.z + w.w * x3.w;
        s  += (w.x + w.y) + (w.z + w.w);
    }
    #pragma unroll
    for (int o = 16; o; o >>= 1) {
        a0 += __shfl_down_sync(0xffffffffu, a0, o);
        a1 += __shfl_down_sync(0xffffffffu, a1, o);
        a2 += __shfl_down_sync(0xffffffffu, a2, o);
        a3 += __shfl_down_sync(0xffffffffu, a3, o);
        s  += __shfl_down_sync(0xffffffffu, s,  o);
    }
    if (lane == 0) {
        float bh = b_head[p];
        out[(b0 + 0) * PRED + p] = bh + g_mean[b0 + 0] * s + g_std[b0 + 0] * a0;
        out[(b0 + 1) * PRED + p] = bh + g_mean[b0 + 1] * s + g_std[b0 + 1] * a1;
        out[(b0 + 2) * PRED + p] = bh + g_mean[b0 + 2] * s + g_std[b0 + 2] * a2;
        out[(b0 + 3) * PRED + p] = bh + g_mean[b0 + 3] * s + g_std[b0 + 3] * a3;
    }
}

// ---------------- launch ----------------
extern "C" void kernel_launch(void* const* d_in, const int* in_sizes, int n_in,
                              void* d_out, int out_size) {
    const float* x         = (const float*)d_in[0];
    const float* W_proj    = (const float*)d_in[4];
    const float* b_proj    = (const float*)d_in[5];
    const float* W_router  = (const float*)d_in[6];
    const float* b_router  = (const float*)d_in[7];
    const float* W_experts = (const float*)d_in[8];
    const float* b_experts = (const float*)d_in[9];
    const float* W_head    = (const float*)d_in[10];
    const float* b_head    = (const float*)d_in[11];
    float* out = (float*)d_out;

    k_prep<<<160, 256>>>(W_experts, x, W_proj, b_proj, W_router, b_router);
    k_expert<<<128, 256>>>(b_experts);
    k_head<<<dim3(12, 8), 256>>>(W_head, b_head, out);
}

// round 14
// speedup vs baseline: 2.9566x; 2.9566x over previous
#include <cuda_runtime.h>
#include <math.h>

#define BB   32      // batch
#define LL   1024    // seq len
#define CC   34      // channels in x
#define DD   256     // model dim
#define EE   8       // experts
#define NQ   4       // patches that survive truncation (1024/256)
#define TT   (BB*NQ) // 128 token-patches
#define PRED 96

// ---------------- scratch (no allocations allowed) ----------------
__device__ float g_mean[BB];
__device__ float g_std[BB];
__device__ float g_xp[TT][DD];        // projected patches
__device__ float g_gates[TT][EE];     // router gates
__device__ float g_comb[TT][DD];      // gate-combined expert output
__device__ float g_Wt[EE][DD][DD];    // W_experts transposed: [e][d][h]

// packed fp32x2 helpers
__device__ __forceinline__ unsigned long long pack2(float lo, float hi) {
    unsigned long long r;
    asm("mov.b64 %0, {%1, %2};" : "=l"(r) : "f"(lo), "f"(hi));
    return r;
}
__device__ __forceinline__ void unpack2(unsigned long long v, float& lo, float& hi) {
    asm("mov.b64 {%0, %1}, %2;" : "=f"(lo), "=f"(hi) : "l"(v));
}
__device__ __forceinline__ unsigned long long fma2(unsigned long long a,
                                                   unsigned long long b,
                                                   unsigned long long c) {
    unsigned long long r;
    asm("fma.rn.f32x2 %0, %1, %2, %3;" : "=l"(r) : "l"(a), "l"(b), "l"(c));
    return r;
}

// ---------------- K1: fused (stats+proj+router) || float4 transpose ----------------
union SmemU {
    struct { float tile[64][65]; } tr;
    struct {
        float Wp_t[16][DD + 1];
        float Wr[EE][DD];
        float xc[64];
        float xp[NQ][DD];
        float red[2][8];
        float logit[32];
        float mean, std;
    } st;
};

__global__ __launch_bounds__(256) void k_prep(const float* __restrict__ W,
                                              const float* __restrict__ x,
                                              const float* __restrict__ W_proj,
                                              const float* __restrict__ b_proj,
                                              const float* __restrict__ W_router,
                                              const float* __restrict__ b_router)
{
    __shared__ SmemU sm;
    int bid = blockIdx.x, tid = threadIdx.x;

    if (bid >= 32) {
        // ---- float4 transpose of one 64x64 tile ----
        int tl  = bid - 32;              // 0..127
        int e   = tl >> 4;
        int rem = tl & 15;
        int h0  = (rem >> 2) * 64;
        int d0  = (rem & 3) * 64;
        const float* We = W + e * DD * DD;

        int c4 = tid & 15, r = tid >> 4;
        float4 v[4];
        #pragma unroll
        for (int i = 0; i < 4; i++)
            v[i] = *(const float4*)&We[(h0 + r + 16 * i) * DD + d0 + c4 * 4];
        #pragma unroll
        for (int i = 0; i < 4; i++) {
            int row = r + 16 * i;
            sm.tr.tile[row][c4 * 4 + 0] = v[i].x;
            sm.tr.tile[row][c4 * 4 + 1] = v[i].y;
            sm.tr.tile[row][c4 * 4 + 2] = v[i].z;
            sm.tr.tile[row][c4 * 4 + 3] = v[i].w;
        }
        __syncthreads();
        int hc4 = tid & 15, dr = tid >> 4;
        #pragma unroll
        for (int i = 0; i < 4; i++) {
            int dl = dr + 16 * i;
            float4 o;
            o.x = sm.tr.tile[hc4 * 4 + 0][dl];
            o.y = sm.tr.tile[hc4 * 4 + 1][dl];
            o.z = sm.tr.tile[hc4 * 4 + 2][dl];
            o.w = sm.tr.tile[hc4 * 4 + 3][dl];
            *(float4*)&g_Wt[e][d0 + dl][h0 + hc4 * 4] = o;
        }
#if __CUDA_ARCH__ >= 900
        cudaTriggerProgrammaticLaunchCompletion();
#endif
        return;
    }

    // ---- stats + proj + router path ----
    int b = bid;
    #pragma unroll
    for (int i = 0; i < 16; i++) {
        int idx = tid + i * 256;            // idx = d*16 + j
        sm.st.Wp_t[idx & 15][idx >> 4] = W_proj[idx];
    }
    #pragma unroll
    for (int i = 0; i < 8; i++) {
        int idx = tid + i * 256;
        sm.st.Wr[idx >> 8][idx & 255] = W_router[idx];
    }

    const float* xb = x + (long)b * LL * CC + 2;
    float v0 = xb[(tid      ) * CC];
    float v1 = xb[(tid + 256) * CC];
    float v2 = xb[(tid + 512) * CC];
    float v3 = xb[(tid + 768) * CC];
    float s1 = v0 + v1 + v2 + v3;
    float s2 = v0*v0 + v1*v1 + v2*v2 + v3*v3;
    #pragma unroll
    for (int o = 16; o; o >>= 1) {
        s1 += __shfl_down_sync(0xffffffffu, s1, o);
        s2 += __shfl_down_sync(0xffffffffu, s2, o);
    }
    if ((tid & 31) == 0) { sm.st.red[0][tid >> 5] = s1; sm.st.red[1][tid >> 5] = s2; }
    __syncthreads();
    if (tid == 0) {
        float a = 0.f, c = 0.f;
        #pragma unroll
        for (int i = 0; i < 8; i++) { a += sm.st.red[0][i]; c += sm.st.red[1][i]; }
        float m   = a / (float)LL;
        float var = c / (float)LL - m * m;
        float sd  = sqrtf(var + 1e-5f);
        sm.st.mean = m; sm.st.std = sd;
        g_mean[b] = m; g_std[b] = sd;
    }
    __syncthreads();
    float m = sm.st.mean, sd = sm.st.std;
    if (tid < 64) sm.st.xc[tid] = (v0 - m) / sd;   // v0 holds l = tid
    __syncthreads();

    // xp[q][d], thread owns d = tid
    float bp = b_proj[tid];
    #pragma unroll
    for (int q = 0; q < NQ; q++) {
        float acc = bp;
        #pragma unroll
        for (int j = 0; j < 16; j++)
            acc += sm.st.Wp_t[j][tid] * sm.st.xc[q * 16 + j];
        sm.st.xp[q][tid] = acc;
        g_xp[b * NQ + q][tid] = acc;
    }
    __syncthreads();

    // router logits: thread = (pair = tid>>3, k = tid&7)
    {
        int pair = tid >> 3, k = tid & 7;
        int q = pair >> 3, e = pair & 7;
        float acc = 0.f;
        #pragma unroll
        for (int i = 0; i < 32; i++) {
            int ii = (i + tid) & 31;
            int d = k * 32 + ii;
            acc += sm.st.Wr[e][d] * sm.st.xp[q][d];
        }
        acc += __shfl_down_sync(0xffffffffu, acc, 4, 8);
        acc += __shfl_down_sync(0xffffffffu, acc, 2, 8);
        acc += __shfl_down_sync(0xffffffffu, acc, 1, 8);
        if (k == 0) sm.st.logit[pair] = acc + b_router[e];
    }
    __syncthreads();
    if (tid < NQ) {
        int q = tid;
        float mx = -1e30f;
        #pragma unroll
        for (int e = 0; e < 8; e++) mx = fmaxf(mx, sm.st.logit[q * 8 + e]);
        float s = 0.f, ex[8];
        #pragma unroll
        for (int e = 0; e < 8; e++) { ex[e] = __expf(sm.st.logit[q * 8 + e] - mx); s += ex[e]; }
        float inv = 1.f / s;
        #pragma unroll
        for (int e = 0; e < 8; e++) g_gates[b * NQ + q][e] = ex[e] * inv;
    }
#if __CUDA_ARCH__ >= 900
    cudaTriggerProgrammaticLaunchCompletion();
#endif
}

// ---------------- K2: expert GEMM + gate-combine (R7 known-good) ----------------
// grid = 8 token-tiles (16 tokens) x 16 h-tiles (16 h) = 128 CTAs, 128 threads.
// thread = (e = tid>>4, hl = tid&15); 16 tokens = 8 f32x2 accumulators.
__global__ __launch_bounds__(128) void k_expert(const float* __restrict__ b_experts)
{
    __shared__ float xps[DD][18];      // [d][t] (stride 18: 8B-aligned, low conflict)
    __shared__ float g_sh[16][EE];     // [t][e]
    __shared__ float sred[EE][16][17]; // [e][h][t] (conflict-free)

    int bx = blockIdx.x;
    int tt = bx >> 4;          // token tile 0..7
    int ht = bx & 15;          // h tile 0..15
    int t0 = tt * 16, h0 = ht * 16;
    int tid = threadIdx.x;

#if __CUDA_ARCH__ >= 900
    cudaGridDependencySynchronize();   // wait for g_xp / g_gates / g_Wt
#endif

    // stage xp transposed: 16 tokens x 256 d
    #pragma unroll
    for (int k = 0; k < 32; k++) {
        int idx = tid + k * 128;         // 4096
        int t = idx >> 8, d = idx & 255;
        xps[d][t] = g_xp[t0 + t][d];
    }
    g_sh[tid >> 3][tid & 7] = g_gates[t0 + (tid >> 3)][tid & 7];
    __syncthreads();

    int e = tid >> 4;
    int hl = tid & 15;
    const float* wp = &g_Wt[e][0][h0 + hl];
    unsigned long long a0=0,a1=0,a2=0,a3=0,a4=0,a5=0,a6=0,a7=0;
    #pragma unroll 8
    for (int d = 0; d < DD; d++) {
        float w = wp[(long)d * DD];
        unsigned long long w2 = pack2(w, w);
        const unsigned long long* xp2 = (const unsigned long long*)&xps[d][0];
        a0 = fma2(w2, xp2[0], a0);
        a1 = fma2(w2, xp2[1], a1);
        a2 = fma2(w2, xp2[2], a2);
        a3 = fma2(w2, xp2[3], a3);
        a4 = fma2(w2, xp2[4], a4);
        a5 = fma2(w2, xp2[5], a5);
        a6 = fma2(w2, xp2[6], a6);
        a7 = fma2(w2, xp2[7], a7);
    }
    float acc[16];
    unpack2(a0, acc[0],  acc[1]);
    unpack2(a1, acc[2],  acc[3]);
    unpack2(a2, acc[4],  acc[5]);
    unpack2(a3, acc[6],  acc[7]);
    unpack2(a4, acc[8],  acc[9]);
    unpack2(a5, acc[10], acc[11]);
    unpack2(a6, acc[12], acc[13]);
    unpack2(a7, acc[14], acc[15]);

    float be = b_experts[e * DD + h0 + hl];
    #pragma unroll
    for (int t = 0; t < 16; t++)
        sred[e][hl][t] = g_sh[t][e] * (acc[t] + be);
    __syncthreads();

    // combine over e: thread = (tq = tid>>4, h = tid&15); two t values each
    int tq = tid >> 4, oh = tid & 15;
    #pragma unroll
    for (int half = 0; half < 2; half++) {
        int t = tq + half * 8;
        float s = 0.f;
        #pragma unroll
        for (int e2 = 0; e2 < EE; e2++) s += sred[e2][oh][t];
        g_comb[t0 + t][h0 + oh] = s;
    }
#if __CUDA_ARCH__ >= 900
    cudaTriggerProgrammaticLaunchCompletion();
#endif
}

// ---------------- K3: head GEMV, grid = 12 p-tiles x 8 b-quads ----------------
__global__ __launch_bounds__(256) void k_head(
    const float* __restrict__ W_head, const float* __restrict__ b_head,
    float* __restrict__ out)
{
    __shared__ float fl[4][LL];
    int pt = blockIdx.x;          // 0..11
    int bq = blockIdx.y;          // 0..7
    int b0 = bq * 4;
    int tid = threadIdx.x;

#if __CUDA_ARCH__ >= 900
    cudaGridDependencySynchronize();   // wait for g_comb / g_mean / g_std
#endif

    #pragma unroll
    for (int i = 0; i < 16; i++) {
        int idx = tid + i * 256;               // 4096 = 4 b * 1024
        int bb = idx >> 10, l = idx & 1023;
        fl[bb][l] = g_comb[(b0 + bb) * NQ + (l >> 8)][l & 255];
    }
    __syncthreads();

    int warp = tid >> 5, lane = tid & 31;
    int p = pt * 8 + warp;
    const float4* W4 = (const float4*)(W_head + p * LL);
    const float4* f0 = (const float4*)fl[0];
    const float4* f1 = (const float4*)fl[1];
    const float4* f2 = (const float4*)fl[2];
    const float4* f3 = (const float4*)fl[3];

    float a0 = 0.f, a1 = 0.f, a2 = 0.f, a3 = 0.f, s = 0.f;
    #pragma unroll
    for (int i = 0; i < 8; i++) {
        int off = i * 32 + lane;
        float4 w = W4[off];                    // coalesced 512B
        float4 x0 = f0[off], x1 = f1[off], x2 = f2[off], x3 = f3[off];
        a0 += w.x * x0.x + w.y * x0.y + w.z * x0.z + w.w * x0.w;
        a1 += w.x * x1.x + w.y * x1.y + w.z * x1.z + w.w * x1.w;
        a2 += w.x * x2.x + w.y * x2.y + w.z * x2.z + w.w * x2.w;
        a3 += w.x * x3.x + w.y * x3.y + w.z * x3.z + w.w * x3.w;
        s  += (w.x + w.y) + (w.z + w.w);
    }
    #pragma unroll
    for (int o = 16; o; o >>= 1) {
        a0 += __shfl_down_sync(0xffffffffu, a0, o);
        a1 += __shfl_down_sync(0xffffffffu, a1, o);
        a2 += __shfl_down_sync(0xffffffffu, a2, o);
        a3 += __shfl_down_sync(0xffffffffu, a3, o);
        s  += __shfl_down_sync(0xffffffffu, s,  o);
    }
    if (lane == 0) {
        float bh = b_head[p];
        out[(b0 + 0) * PRED + p] = bh + g_mean[b0 + 0] * s + g_std[b0 + 0] * a0;
        out[(b0 + 1) * PRED + p] = bh + g_mean[b0 + 1] * s + g_std[b0 + 1] * a1;
        out[(b0 + 2) * PRED + p] = bh + g_mean[b0 + 2] * s + g_std[b0 + 2] * a2;
        out[(b0 + 3) * PRED + p] = bh + g_mean[b0 + 3] * s + g_std[b0 + 3] * a3;
    }
}

// ---------------- launch (PDL chain) ----------------
extern "C" void kernel_launch(void* const* d_in, const int* in_sizes, int n_in,
                              void* d_out, int out_size) {
    const float* x         = (const float*)d_in[0];
    const float* W_proj    = (const float*)d_in[4];
    const float* b_proj    = (const float*)d_in[5];
    const float* W_router  = (const float*)d_in[6];
    const float* b_router  = (const float*)d_in[7];
    const float* W_experts = (const float*)d_in[8];
    const float* b_experts = (const float*)d_in[9];
    const float* W_head    = (const float*)d_in[10];
    const float* b_head    = (const float*)d_in[11];
    float* out = (float*)d_out;

    k_prep<<<160, 256>>>(W_experts, x, W_proj, b_proj, W_router, b_router);

    cudaLaunchAttribute attr[1];
    attr[0].id = cudaLaunchAttributeProgrammaticStreamSerialization;
    attr[0].val.programmaticStreamSerializationAllowed = 1;

    {
        cudaLaunchConfig_t cfg = {};
        cfg.gridDim  = dim3(128, 1, 1);
        cfg.blockDim = dim3(128, 1, 1);
        cfg.attrs = attr;
        cfg.numAttrs = 1;
        cudaLaunchKernelEx(&cfg, k_expert, b_experts);
    }
    {
        cudaLaunchConfig_t cfg = {};
        cfg.gridDim  = dim3(12, 8, 1);
        cfg.blockDim = dim3(256, 1, 1);
        cfg.attrs = attr;
        cfg.numAttrs = 1;
        cudaLaunchKernelEx(&cfg, k_head, W_head, b_head, out);
    }
}